// round 1
// baseline (speedup 1.0000x reference)
#include <cuda_runtime.h>
#include <cuda_bf16.h>
#include <math.h>

// ---------------------------------------------------------------------------
// Swin Transformer block: B=32, H=W=56, C=384, 12 heads, window 7, shift 3
// ---------------------------------------------------------------------------
#define Bb    32
#define Hh    56
#define Ww    56
#define Cc    384
#define HEADS 12
#define WS    7
#define SHIFT 3
#define HD    32
#define NTOK  49            // WS*WS
#define NWIN  64            // (56/7)^2 windows per image
#define ROWS  100352        // B*H*W = B*NWIN*NTOK
#define C3    1152          // 3*C
#define CH    1536          // 4*C
#define SCALE 0.17677669529663687f   // 32^-0.5
#define LNEPS 1e-5f

// Scratch (static device memory — no allocation at runtime)
__device__ float g_win[(size_t)ROWS * Cc];    // LN1 windowed rows / LN2 rows
__device__ float g_qkv[(size_t)ROWS * C3];
__device__ float g_xa [(size_t)ROWS * Cc];
__device__ float g_m1 [(size_t)ROWS * CH];

// ---------------------------------------------------------------------------
// LayerNorm kernel. gather==1: dest row r is a window-ordered row, source is
// the shifted original token (LN1 + roll(-3,-3) + window partition fused).
// gather==0: identity rows (LN2).
// ---------------------------------------------------------------------------
__global__ void __launch_bounds__(128) ln_kernel(
    const float* __restrict__ x, const float* __restrict__ g,
    const float* __restrict__ bt, float* __restrict__ out, int gather)
{
    int r = blockIdx.x;
    int src = r;
    if (gather) {
        int n  = r % NTOK;
        int wl = (r / NTOK) % NWIN;
        int b  = r / (NTOK * NWIN);
        int wh = wl >> 3, ww = wl & 7;
        int i  = n / WS,  j  = n % WS;
        int oh = (wh * WS + i + SHIFT) % Hh;
        int ow = (ww * WS + j + SHIFT) % Ww;
        src = b * (Hh * Ww) + oh * Ww + ow;
    }
    const float* xp = x + (size_t)src * Cc;
    int tid = threadIdx.x;
    float v[3];
#pragma unroll
    for (int q = 0; q < 3; q++) v[q] = xp[tid + q * 128];
    float s  = v[0] + v[1] + v[2];
    float s2 = v[0]*v[0] + v[1]*v[1] + v[2]*v[2];
#pragma unroll
    for (int o = 16; o; o >>= 1) {
        s  += __shfl_xor_sync(0xffffffffu, s,  o);
        s2 += __shfl_xor_sync(0xffffffffu, s2, o);
    }
    __shared__ float sh[8];
    int wid = tid >> 5, lane = tid & 31;
    if (lane == 0) { sh[wid] = s; sh[wid + 4] = s2; }
    __syncthreads();
    float mu  = (sh[0] + sh[1] + sh[2] + sh[3]) * (1.0f / Cc);
    float var = (sh[4] + sh[5] + sh[6] + sh[7]) * (1.0f / Cc) - mu * mu;
    float rstd = rsqrtf(var + LNEPS);
    float* op = out + (size_t)r * Cc;
#pragma unroll
    for (int q = 0; q < 3; q++) {
        int c = tid + q * 128;
        op[c] = (v[q] - mu) * rstd * g[c] + bt[c];
    }
}

// ---------------------------------------------------------------------------
// Tiled SGEMM: C = A[M,K] @ B[K,N] + bias, with fused epilogues.
// BM=BN=64, BK=16, 256 threads, 4x4 per-thread microtile.
// All M/N/K here are exact multiples of the tiles — no bounds checks.
// EPI 0: plain store.  EPI 1: window-reverse+unshift scatter + shortcut add.
// EPI 2: exact GELU.   EPI 3: residual add into Cout.
// ---------------------------------------------------------------------------
__device__ __forceinline__ int winrev_map(int m)
{
    int n  = m % NTOK;
    int wl = (m / NTOK) % NWIN;
    int b  = m / (NTOK * NWIN);
    int wh = wl >> 3, ww = wl & 7;
    int i  = n / WS,  j  = n % WS;
    int oh = (wh * WS + i + SHIFT) % Hh;
    int ow = (ww * WS + j + SHIFT) % Ww;
    return b * (Hh * Ww) + oh * Ww + ow;
}

template <int EPI>
__global__ void __launch_bounds__(256) sgemm_kernel(
    const float* __restrict__ A, const float* __restrict__ Bw,
    const float* __restrict__ bias, float* __restrict__ Cout,
    int M, int Nn, int K, const float* __restrict__ add_src)
{
    const int BM = 64, BN = 64, BK = 16;
    __shared__ float As[BK][BM];
    __shared__ float Bs[BK][BN];
    int m0 = blockIdx.y * BM;
    int n0 = blockIdx.x * BN;
    int tx = threadIdx.x, ty = threadIdx.y;       // 16 x 16
    int tid = ty * 16 + tx;
    int a_m = tid >> 2;            // 0..63
    int a_k = (tid & 3) * 4;       // 0,4,8,12
    int b_k = tid >> 4;            // 0..15
    int b_n = (tid & 15) * 4;      // 0..60
    float acc[4][4] = {};

    for (int k0 = 0; k0 < K; k0 += BK) {
        float4 av = *(const float4*)(A + (size_t)(m0 + a_m) * K + k0 + a_k);
        As[a_k + 0][a_m] = av.x; As[a_k + 1][a_m] = av.y;
        As[a_k + 2][a_m] = av.z; As[a_k + 3][a_m] = av.w;
        float4 bv = *(const float4*)(Bw + (size_t)(k0 + b_k) * Nn + n0 + b_n);
        *(float4*)&Bs[b_k][b_n] = bv;
        __syncthreads();
#pragma unroll
        for (int kk = 0; kk < BK; kk++) {
            float a[4], b[4];
#pragma unroll
            for (int i = 0; i < 4; i++) a[i] = As[kk][ty * 4 + i];
#pragma unroll
            for (int j = 0; j < 4; j++) b[j] = Bs[kk][tx * 4 + j];
#pragma unroll
            for (int i = 0; i < 4; i++)
#pragma unroll
                for (int j = 0; j < 4; j++) acc[i][j] += a[i] * b[j];
        }
        __syncthreads();
    }

    int n_base = n0 + tx * 4;
#pragma unroll
    for (int i = 0; i < 4; i++) {
        int m = m0 + ty * 4 + i;
        int dest = (EPI == 1) ? winrev_map(m) : m;
#pragma unroll
        for (int j = 0; j < 4; j++) {
            int n = n_base + j;
            float v = acc[i][j] + bias[n];
            if (EPI == 0) {
                Cout[(size_t)m * Nn + n] = v;
            } else if (EPI == 1) {
                size_t idx = (size_t)dest * Cc + n;
                Cout[idx] = add_src[idx] + v;
            } else if (EPI == 2) {
                Cout[(size_t)m * Nn + n] = 0.5f * v * (1.0f + erff(v * 0.70710678118654752f));
            } else { // EPI == 3
                size_t idx = (size_t)m * Nn + n;
                Cout[idx] = add_src[idx] + v;
            }
        }
    }
}

// ---------------------------------------------------------------------------
// Windowed attention: one block per (window, head). N=49, HD=32.
// q/k/v staged in SMEM; per-thread row softmax; rel-pos bias and shift mask
// computed on the fly.
// ---------------------------------------------------------------------------
__global__ void __launch_bounds__(64) attn_kernel(
    const float* __restrict__ qkv, const float* __restrict__ rpb,
    float* __restrict__ xa)
{
    int head = blockIdx.x;    // 12
    int bwin = blockIdx.y;    // 2048
    __shared__ float qs[NTOK * HD], ks[NTOK * HD], vs[NTOK * HD];
    int tid = threadIdx.x;

    const float* base = qkv + (size_t)bwin * NTOK * C3 + head * HD;
    for (int idx = tid; idx < NTOK * HD; idx += 64) {
        int n = idx >> 5, d = idx & 31;
        size_t off = (size_t)n * C3 + d;
        qs[idx] = base[off];
        ks[idx] = base[off + Cc];
        vs[idx] = base[off + 2 * Cc];
    }
    __syncthreads();

    if (tid < NTOK) {
        int n = tid;
        float q[HD];
#pragma unroll
        for (int d = 0; d < HD; d++) q[d] = qs[n * HD + d] * SCALE;

        int in_ = n / WS, jn = n % WS;
        int wl = bwin & (NWIN - 1);
        int wh = wl >> 3, ww = wl & 7;
        int hs_n = wh * WS + in_, ws_n = ww * WS + jn;
        int lab_n = (hs_n < Hh - WS ? 0 : (hs_n < Hh - SHIFT ? 1 : 2)) * 3
                  + (ws_n < Ww - WS ? 0 : (ws_n < Ww - SHIFT ? 1 : 2));

        float s[NTOK];
        float mx = -1e30f;
        for (int m = 0; m < NTOK; m++) {
            float dot = 0.0f;
#pragma unroll
            for (int d = 0; d < HD; d++) dot += q[d] * ks[m * HD + d];
            int im = m / WS, jm = m % WS;
            int hs_m = wh * WS + im, ws_m = ww * WS + jm;
            int lab_m = (hs_m < Hh - WS ? 0 : (hs_m < Hh - SHIFT ? 1 : 2)) * 3
                      + (ws_m < Ww - WS ? 0 : (ws_m < Ww - SHIFT ? 1 : 2));
            int rel = (in_ - im + WS - 1) * (2 * WS - 1) + (jn - jm + WS - 1);
            dot += rpb[rel * HEADS + head];
            if (lab_m != lab_n) dot -= 100.0f;
            s[m] = dot;
            mx = fmaxf(mx, dot);
        }
        float sum = 0.0f;
        for (int m = 0; m < NTOK; m++) { s[m] = __expf(s[m] - mx); sum += s[m]; }
        float inv = 1.0f / sum;

        float o[HD];
#pragma unroll
        for (int d = 0; d < HD; d++) o[d] = 0.0f;
        for (int m = 0; m < NTOK; m++) {
            float p = s[m] * inv;
#pragma unroll
            for (int d = 0; d < HD; d++) o[d] += p * vs[m * HD + d];
        }
        float* dst = xa + ((size_t)bwin * NTOK + n) * Cc + head * HD;
#pragma unroll
        for (int d = 0; d < HD; d++) dst[d] = o[d];
    }
}

// ---------------------------------------------------------------------------
// Launch
// ---------------------------------------------------------------------------
extern "C" void kernel_launch(void* const* d_in, const int* in_sizes, int n_in,
                              void* d_out, int out_size)
{
    const float* x      = (const float*)d_in[0];
    const float* ln1_g  = (const float*)d_in[1];
    const float* ln1_b  = (const float*)d_in[2];
    const float* qkv_w  = (const float*)d_in[3];
    const float* qkv_b  = (const float*)d_in[4];
    const float* rpb    = (const float*)d_in[5];
    const float* proj_w = (const float*)d_in[6];
    const float* proj_b = (const float*)d_in[7];
    const float* ln2_g  = (const float*)d_in[8];
    const float* ln2_b  = (const float*)d_in[9];
    const float* fc1_w  = (const float*)d_in[10];
    const float* fc1_b  = (const float*)d_in[11];
    const float* fc2_w  = (const float*)d_in[12];
    const float* fc2_b  = (const float*)d_in[13];
    float* out = (float*)d_out;

    float *p_win, *p_qkv, *p_xa, *p_m1;
    cudaGetSymbolAddress((void**)&p_win, g_win);
    cudaGetSymbolAddress((void**)&p_qkv, g_qkv);
    cudaGetSymbolAddress((void**)&p_xa,  g_xa);
    cudaGetSymbolAddress((void**)&p_m1,  g_m1);

    dim3 t16(16, 16);

    // 1. LN1 + shift + window partition
    ln_kernel<<<ROWS, 128>>>(x, ln1_g, ln1_b, p_win, 1);

    // 2. qkv GEMM: [ROWS,384] @ [384,1152]
    sgemm_kernel<0><<<dim3(C3 / 64, ROWS / 64), t16>>>(p_win, qkv_w, qkv_b, p_qkv,
                                                       ROWS, C3, Cc, nullptr);

    // 3. windowed attention
    attn_kernel<<<dim3(HEADS, ROWS / NTOK), 64>>>(p_qkv, rpb, p_xa);

    // 4. proj GEMM + window reverse + unshift + shortcut add -> d_out
    sgemm_kernel<1><<<dim3(Cc / 64, ROWS / 64), t16>>>(p_xa, proj_w, proj_b, out,
                                                       ROWS, Cc, Cc, x);

    // 5. LN2 on d_out
    ln_kernel<<<ROWS, 128>>>(out, ln2_g, ln2_b, p_win, 0);

    // 6. fc1 GEMM + GELU: [ROWS,384] @ [384,1536]
    sgemm_kernel<2><<<dim3(CH / 64, ROWS / 64), t16>>>(p_win, fc1_w, fc1_b, p_m1,
                                                       ROWS, CH, Cc, nullptr);

    // 7. fc2 GEMM + residual add: [ROWS,1536] @ [1536,384]
    sgemm_kernel<3><<<dim3(Cc / 64, ROWS / 64), t16>>>(p_m1, fc2_w, fc2_b, out,
                                                       ROWS, Cc, CH, out);
}

// round 2
// speedup vs baseline: 2.9510x; 2.9510x over previous
#include <cuda_runtime.h>
#include <cuda_bf16.h>
#include <math.h>
#include <stdint.h>

// ---------------------------------------------------------------------------
// Swin Transformer block: B=32, H=W=56, C=384, 12 heads, window 7, shift 3
// ---------------------------------------------------------------------------
#define Bb    32
#define Hh    56
#define Ww    56
#define Cc    384
#define HEADS 12
#define WS    7
#define SHIFT 3
#define HD    32
#define NTOK  49
#define NWIN  64
#define ROWS  100352
#define C3    1152
#define CH    1536
#define SCALE 0.17677669529663687f
#define LNEPS 1e-5f

// Scratch (static device memory — no allocation at runtime)
__device__ float g_win[(size_t)ROWS * Cc];
__device__ float g_qkv[(size_t)ROWS * C3];
__device__ float g_xa [(size_t)ROWS * Cc];
__device__ float g_m1 [(size_t)ROWS * CH];

// ---------------------------------------------------------------------------
// LayerNorm (fused shift+window-partition gather when gather==1)
// ---------------------------------------------------------------------------
__global__ void __launch_bounds__(128) ln_kernel(
    const float* __restrict__ x, const float* __restrict__ g,
    const float* __restrict__ bt, float* __restrict__ out, int gather)
{
    int r = blockIdx.x;
    int src = r;
    if (gather) {
        int n  = r % NTOK;
        int wl = (r / NTOK) % NWIN;
        int b  = r / (NTOK * NWIN);
        int wh = wl >> 3, ww = wl & 7;
        int i  = n / WS,  j  = n % WS;
        int oh = (wh * WS + i + SHIFT) % Hh;
        int ow = (ww * WS + j + SHIFT) % Ww;
        src = b * (Hh * Ww) + oh * Ww + ow;
    }
    const float* xp = x + (size_t)src * Cc;
    int tid = threadIdx.x;
    float v[3];
#pragma unroll
    for (int q = 0; q < 3; q++) v[q] = xp[tid + q * 128];
    float s  = v[0] + v[1] + v[2];
    float s2 = v[0]*v[0] + v[1]*v[1] + v[2]*v[2];
#pragma unroll
    for (int o = 16; o; o >>= 1) {
        s  += __shfl_xor_sync(0xffffffffu, s,  o);
        s2 += __shfl_xor_sync(0xffffffffu, s2, o);
    }
    __shared__ float sh[8];
    int wid = tid >> 5, lane = tid & 31;
    if (lane == 0) { sh[wid] = s; sh[wid + 4] = s2; }
    __syncthreads();
    float mu  = (sh[0] + sh[1] + sh[2] + sh[3]) * (1.0f / Cc);
    float var = (sh[4] + sh[5] + sh[6] + sh[7]) * (1.0f / Cc) - mu * mu;
    float rstd = rsqrtf(var + LNEPS);
    float* op = out + (size_t)r * Cc;
#pragma unroll
    for (int q = 0; q < 3; q++) {
        int c = tid + q * 128;
        op[c] = (v[q] - mu) * rstd * g[c] + bt[c];
    }
}

__device__ __forceinline__ int winrev_map(int m)
{
    int n  = m % NTOK;
    int wl = (m / NTOK) % NWIN;
    int b  = m / (NTOK * NWIN);
    int wh = wl >> 3, ww = wl & 7;
    int i  = n / WS,  j  = n % WS;
    int oh = (wh * WS + i + SHIFT) % Hh;
    int ow = (ww * WS + j + SHIFT) % Ww;
    return b * (Hh * Ww) + oh * Ww + ow;
}

__device__ __forceinline__ uint32_t f2tf32(float x)
{
    uint32_t u;
    asm("cvt.rna.tf32.f32 %0, %1;" : "=r"(u) : "f"(x));
    return u;
}

// ---------------------------------------------------------------------------
// TF32 tensor-core GEMM: C = A[M,K] @ B[K,N] + bias (+ fused epilogues)
// Block tile 128x128x16, 8 warps, warp tile 64x32 via mma.sync.m16n8k8.tf32.
// SMEM pads chosen for conflict-free fragment loads:
//   A[128][20]: bank (20m+k)%32 distinct over (m in 0..7, k in 0..3)
//   B[16][136]: bank (8k+n)%32 distinct over (k in 0..3, n in 0..7)
// EPI 0: store. 1: window-reverse scatter + shortcut add. 2: GELU. 3: res add.
// ---------------------------------------------------------------------------
template <int EPI>
__global__ void __launch_bounds__(256) mma_gemm(
    const float* __restrict__ A, const float* __restrict__ Bw,
    const float* __restrict__ bias, float* __restrict__ Cout,
    int M, int N, int K, const float* __restrict__ add_src)
{
    const int tid  = threadIdx.x;
    const int lane = tid & 31;
    const int wid  = tid >> 5;
    const int wm   = (wid & 1) * 64;   // warp row offset in tile
    const int wn   = (wid >> 1) * 32;  // warp col offset in tile
    const int m0   = blockIdx.y * 128;
    const int n0   = blockIdx.x * 128;

    // global load mapping
    const int raw = tid >> 2;           // A row 0..63 (and +64)
    const int rac = (tid & 3) * 4;      // A col 0,4,8,12
    const int rbw = tid >> 5;           // B row 0..7 (and +8)
    const int rbc = (tid & 31) * 4;     // B col 0..124
    const float* gA0 = A + (size_t)(m0 + raw) * K + rac;
    const float* gA1 = gA0 + (size_t)64 * K;
    const float* gB0 = Bw + (size_t)rbw * N + n0 + rbc;
    const float* gB1 = gB0 + (size_t)8 * N;

    __shared__ uint32_t sA[2][128 * 20];
    __shared__ uint32_t sB[2][16 * 136];

    float4 a0v = *(const float4*)gA0;
    float4 a1v = *(const float4*)gA1;
    float4 b0v = *(const float4*)gB0;
    float4 b1v = *(const float4*)gB1;

    auto sts = [&](int buf) {
        uint4 u;
        u.x = f2tf32(a0v.x); u.y = f2tf32(a0v.y); u.z = f2tf32(a0v.z); u.w = f2tf32(a0v.w);
        *(uint4*)&sA[buf][raw * 20 + rac] = u;
        u.x = f2tf32(a1v.x); u.y = f2tf32(a1v.y); u.z = f2tf32(a1v.z); u.w = f2tf32(a1v.w);
        *(uint4*)&sA[buf][(raw + 64) * 20 + rac] = u;
        u.x = f2tf32(b0v.x); u.y = f2tf32(b0v.y); u.z = f2tf32(b0v.z); u.w = f2tf32(b0v.w);
        *(uint4*)&sB[buf][rbw * 136 + rbc] = u;
        u.x = f2tf32(b1v.x); u.y = f2tf32(b1v.y); u.z = f2tf32(b1v.z); u.w = f2tf32(b1v.w);
        *(uint4*)&sB[buf][(rbw + 8) * 136 + rbc] = u;
    };
    sts(0);
    __syncthreads();

    float c[4][4][4] = {};
    int buf = 0;
    for (int k0 = 0; k0 < K; k0 += 16) {
        const bool pre = (k0 + 16) < K;
        if (pre) {
            a0v = *(const float4*)(gA0 + k0 + 16);
            a1v = *(const float4*)(gA1 + k0 + 16);
            b0v = *(const float4*)(gB0 + (size_t)(k0 + 16) * N);
            b1v = *(const float4*)(gB1 + (size_t)(k0 + 16) * N);
        }
        const uint32_t* pA = sA[buf];
        const uint32_t* pB = sB[buf];
#pragma unroll
        for (int kk = 0; kk < 16; kk += 8) {
            uint32_t af[4][4], bf[4][2];
            int ar = wm + (lane >> 2);
            int ac = kk + (lane & 3);
#pragma unroll
            for (int i = 0; i < 4; i++) {
                int r = ar + i * 16;
                af[i][0] = pA[r * 20 + ac];
                af[i][1] = pA[(r + 8) * 20 + ac];
                af[i][2] = pA[r * 20 + ac + 4];
                af[i][3] = pA[(r + 8) * 20 + ac + 4];
            }
            int bc = wn + (lane >> 2);
            int br = kk + (lane & 3);
#pragma unroll
            for (int j = 0; j < 4; j++) {
                bf[j][0] = pB[br * 136 + bc + j * 8];
                bf[j][1] = pB[(br + 4) * 136 + bc + j * 8];
            }
#pragma unroll
            for (int i = 0; i < 4; i++)
#pragma unroll
                for (int j = 0; j < 4; j++)
                    asm volatile(
                        "mma.sync.aligned.m16n8k8.row.col.f32.tf32.tf32.f32 "
                        "{%0,%1,%2,%3}, {%4,%5,%6,%7}, {%8,%9}, {%0,%1,%2,%3};"
                        : "+f"(c[i][j][0]), "+f"(c[i][j][1]),
                          "+f"(c[i][j][2]), "+f"(c[i][j][3])
                        : "r"(af[i][0]), "r"(af[i][1]), "r"(af[i][2]), "r"(af[i][3]),
                          "r"(bf[j][0]), "r"(bf[j][1]));
        }
        if (pre) sts(buf ^ 1);
        __syncthreads();
        buf ^= 1;
    }

    // epilogue
#pragma unroll
    for (int i = 0; i < 4; i++) {
        int rbase = m0 + wm + i * 16 + (lane >> 2);
#pragma unroll
        for (int half = 0; half < 2; half++) {
            int r = rbase + half * 8;
            int dest = (EPI == 1) ? winrev_map(r) : r;
#pragma unroll
            for (int j = 0; j < 4; j++) {
                int cn = n0 + wn + j * 8 + (lane & 3) * 2;
                float v0 = c[i][j][half * 2 + 0] + bias[cn];
                float v1 = c[i][j][half * 2 + 1] + bias[cn + 1];
                if (EPI == 0) {
                    *(float2*)&Cout[(size_t)r * N + cn] = make_float2(v0, v1);
                } else if (EPI == 1) {
                    size_t idx = (size_t)dest * Cc + cn;
                    *(float2*)&Cout[idx] =
                        make_float2(add_src[idx] + v0, add_src[idx + 1] + v1);
                } else if (EPI == 2) {
                    v0 = 0.5f * v0 * (1.0f + erff(v0 * 0.70710678118654752f));
                    v1 = 0.5f * v1 * (1.0f + erff(v1 * 0.70710678118654752f));
                    *(float2*)&Cout[(size_t)r * N + cn] = make_float2(v0, v1);
                } else { // EPI == 3
                    size_t idx = (size_t)r * N + cn;
                    *(float2*)&Cout[idx] =
                        make_float2(add_src[idx] + v0, add_src[idx + 1] + v1);
                }
            }
        }
    }
}

// ---------------------------------------------------------------------------
// Windowed attention: one block per (window, head). N=49, HD=32.
// ---------------------------------------------------------------------------
__global__ void __launch_bounds__(64) attn_kernel(
    const float* __restrict__ qkv, const float* __restrict__ rpb,
    float* __restrict__ xa)
{
    int head = blockIdx.x;
    int bwin = blockIdx.y;
    __shared__ float qs[NTOK * HD], ks[NTOK * HD], vs[NTOK * HD];
    int tid = threadIdx.x;

    const float* base = qkv + (size_t)bwin * NTOK * C3 + head * HD;
    for (int idx = tid; idx < NTOK * HD; idx += 64) {
        int n = idx >> 5, d = idx & 31;
        size_t off = (size_t)n * C3 + d;
        qs[idx] = base[off];
        ks[idx] = base[off + Cc];
        vs[idx] = base[off + 2 * Cc];
    }
    __syncthreads();

    if (tid < NTOK) {
        int n = tid;
        float q[HD];
#pragma unroll
        for (int d = 0; d < HD; d++) q[d] = qs[n * HD + d] * SCALE;

        int in_ = n / WS, jn = n % WS;
        int wl = bwin & (NWIN - 1);
        int wh = wl >> 3, ww = wl & 7;
        int hs_n = wh * WS + in_, ws_n = ww * WS + jn;
        int lab_n = (hs_n < Hh - WS ? 0 : (hs_n < Hh - SHIFT ? 1 : 2)) * 3
                  + (ws_n < Ww - WS ? 0 : (ws_n < Ww - SHIFT ? 1 : 2));

        float s[NTOK];
        float mx = -1e30f;
        for (int m = 0; m < NTOK; m++) {
            float dot = 0.0f;
#pragma unroll
            for (int d = 0; d < HD; d++) dot += q[d] * ks[m * HD + d];
            int im = m / WS, jm = m % WS;
            int hs_m = wh * WS + im, ws_m = ww * WS + jm;
            int lab_m = (hs_m < Hh - WS ? 0 : (hs_m < Hh - SHIFT ? 1 : 2)) * 3
                      + (ws_m < Ww - WS ? 0 : (ws_m < Ww - SHIFT ? 1 : 2));
            int rel = (in_ - im + WS - 1) * (2 * WS - 1) + (jn - jm + WS - 1);
            dot += rpb[rel * HEADS + head];
            if (lab_m != lab_n) dot -= 100.0f;
            s[m] = dot;
            mx = fmaxf(mx, dot);
        }
        float sum = 0.0f;
        for (int m = 0; m < NTOK; m++) { s[m] = __expf(s[m] - mx); sum += s[m]; }
        float inv = 1.0f / sum;

        float o[HD];
#pragma unroll
        for (int d = 0; d < HD; d++) o[d] = 0.0f;
        for (int m = 0; m < NTOK; m++) {
            float p = s[m] * inv;
#pragma unroll
            for (int d = 0; d < HD; d++) o[d] += p * vs[m * HD + d];
        }
        float* dst = xa + ((size_t)bwin * NTOK + n) * Cc + head * HD;
#pragma unroll
        for (int d = 0; d < HD; d++) dst[d] = o[d];
    }
}

// ---------------------------------------------------------------------------
// Launch
// ---------------------------------------------------------------------------
extern "C" void kernel_launch(void* const* d_in, const int* in_sizes, int n_in,
                              void* d_out, int out_size)
{
    const float* x      = (const float*)d_in[0];
    const float* ln1_g  = (const float*)d_in[1];
    const float* ln1_b  = (const float*)d_in[2];
    const float* qkv_w  = (const float*)d_in[3];
    const float* qkv_b  = (const float*)d_in[4];
    const float* rpb    = (const float*)d_in[5];
    const float* proj_w = (const float*)d_in[6];
    const float* proj_b = (const float*)d_in[7];
    const float* ln2_g  = (const float*)d_in[8];
    const float* ln2_b  = (const float*)d_in[9];
    const float* fc1_w  = (const float*)d_in[10];
    const float* fc1_b  = (const float*)d_in[11];
    const float* fc2_w  = (const float*)d_in[12];
    const float* fc2_b  = (const float*)d_in[13];
    float* out = (float*)d_out;

    float *p_win, *p_qkv, *p_xa, *p_m1;
    cudaGetSymbolAddress((void**)&p_win, g_win);
    cudaGetSymbolAddress((void**)&p_qkv, g_qkv);
    cudaGetSymbolAddress((void**)&p_xa,  g_xa);
    cudaGetSymbolAddress((void**)&p_m1,  g_m1);

    // 1. LN1 + shift + window partition
    ln_kernel<<<ROWS, 128>>>(x, ln1_g, ln1_b, p_win, 1);

    // 2. qkv GEMM: [ROWS,384] @ [384,1152]
    mma_gemm<0><<<dim3(C3 / 128, ROWS / 128), 256>>>(p_win, qkv_w, qkv_b, p_qkv,
                                                     ROWS, C3, Cc, nullptr);

    // 3. windowed attention
    attn_kernel<<<dim3(HEADS, ROWS / NTOK), 64>>>(p_qkv, rpb, p_xa);

    // 4. proj GEMM + window reverse + unshift + shortcut add -> d_out
    mma_gemm<1><<<dim3(Cc / 128, ROWS / 128), 256>>>(p_xa, proj_w, proj_b, out,
                                                     ROWS, Cc, Cc, x);

    // 5. LN2 on d_out
    ln_kernel<<<ROWS, 128>>>(out, ln2_g, ln2_b, p_win, 0);

    // 6. fc1 GEMM + GELU: [ROWS,384] @ [384,1536]
    mma_gemm<2><<<dim3(CH / 128, ROWS / 128), 256>>>(p_win, fc1_w, fc1_b, p_m1,
                                                     ROWS, CH, Cc, nullptr);

    // 7. fc2 GEMM + residual add: [ROWS,1536] @ [1536,384]
    mma_gemm<3><<<dim3(Cc / 128, ROWS / 128), 256>>>(p_m1, fc2_w, fc2_b, out,
                                                     ROWS, Cc, CH, out);
}